// round 2
// baseline (speedup 1.0000x reference)
#include <cuda_runtime.h>

// FourierBlock: out = irfft( scatter( einsum(rfft(q)[bins 1,4,5], W1+iW2) , bins 0..2 ) )
// Shapes: q (B=8, N=2000, L=64, H=4, E=16); weights (N, H, E, E, M=3)
// Only q, weights1, weights2 are used (k, v, mask dead in the reference forward).

#define NB 8
#define NN 2000
#define LL 64
#define HH 4
#define EE 16
#define MM 3

__global__ __launch_bounds__(256) void fourier_block_kernel(
    const float* __restrict__ q,
    const float* __restrict__ w1,
    const float* __restrict__ w2,
    float* __restrict__ out)
{
    const int b   = blockIdx.x;   // batch fastest -> consecutive CTAs share node n's weights in L2
    const int n   = blockIdx.y;
    const int tid = threadIdx.x;  // 256 threads

    __shared__ float sq[LL * HH * EE];     // 4096 floats: q slab, layout [l][h*16+e]
    __shared__ float tc[4 * LL];           // cos(-2*pi*f*l/64), f rows = {1,4,5,2}
    __shared__ float ts[4 * LL];           // sin(-2*pi*f*l/64)
    __shared__ float sXre[3 * 64];         // X[m][h*16+i]
    __shared__ float sXim[3 * 64];
    __shared__ float sYre[3 * 64];         // Y[m][h*16+o]
    __shared__ float sYim[3 * 64];

    const size_t slab = (size_t)(b * NN + n) * (LL * HH * EE);

    // ---- Stage A: coalesced float4 load of q slab (16 KB) ----
    {
        const float4* qp4 = (const float4*)(q + slab);
        float4* sq4 = (float4*)sq;
        #pragma unroll
        for (int r = 0; r < 4; ++r)
            sq4[tid + 256 * r] = qp4[tid + 256 * r];
    }

    // ---- Twiddle tables: rows 0..2 = input freqs {1,4,5}; row 3 = output freq 2 ----
    {
        const int fm[4] = {1, 4, 5, 2};
        int m = tid >> 6, l = tid & 63;
        float ang = -6.28318530717958647692f * (float)(fm[m] * l) * (1.0f / 64.0f);
        tc[tid] = cosf(ang);
        ts[tid] = sinf(ang);
    }
    __syncthreads();

    // ---- Stage B: X[m][hi] = sum_l sq[l][hi] * e^{-i 2 pi f_m l / 64} ----
    if (tid < 192) {
        int m  = tid >> 6;      // 0..2
        int hi = tid & 63;      // h*16 + i
        const float* tcp = tc + (m << 6);
        const float* tsp = ts + (m << 6);
        float re = 0.f, im = 0.f;
        #pragma unroll
        for (int l = 0; l < 64; ++l) {
            float x = sq[(l << 6) + hi];
            re = fmaf(x, tcp[l], re);
            im = fmaf(x, tsp[l], im);
        }
        sXre[tid] = re;
        sXim[tid] = im;
    }
    __syncthreads();

    // ---- Stage C: Y[m][h*16+o] = sum_i X[m][h*16+i] * (W1 + i W2)[n,h,i,o,m] ----
    if (tid < 192) {
        int m  = tid >> 6;
        int ho = tid & 63;
        int h  = ho >> 4;
        int o  = ho & 15;
        const size_t wbase = ((size_t)n * HH + h) * (EE * EE * MM);
        const float* w1p = w1 + wbase;
        const float* w2p = w2 + wbase;
        float yr = 0.f, yi = 0.f;
        #pragma unroll
        for (int i = 0; i < 16; ++i) {
            float xr = sXre[(m << 6) + (h << 4) + i];
            float xi = sXim[(m << 6) + (h << 4) + i];
            int wo = ((i << 4) + o) * MM + m;
            float wr = w1p[wo];
            float wi = w2p[wo];
            yr = fmaf(xr, wr, fmaf(-xi, wi, yr));
            yi = fmaf(xr, wi, fmaf( xi, wr, yi));
        }
        sYre[tid] = yr;
        sYim[tid] = yi;
    }
    __syncthreads();

    // ---- Stage D: irfft with only bins 0,1,2 nonzero (Im of bin 0 ignored) ----
    // out[l] = (Y0r + 2*Re(Y1 e^{+i th l}) + 2*Re(Y2 e^{+i 2 th l})) / 64
    // Using tc/ts rows: row0 stores (cos, -sin) of freq1 -> Re(Y e^{+i}) = Yr*tc + Yi*ts.
    {
        float* op = out + slab;
        #pragma unroll
        for (int r = 0; r < 4; ++r) {
            int f4 = tid + (r << 8);      // float4 index, 0..1023
            int ho = f4 >> 4;             // h*16 + o
            int l0 = (f4 & 15) << 2;      // starting l of this float4
            float y0  = sYre[ho];
            float y1r = sYre[64 + ho],  y1i = sYim[64 + ho];
            float y2r = sYre[128 + ho], y2i = sYim[128 + ho];
            float4 v;
            float* vv = &v.x;
            #pragma unroll
            for (int j = 0; j < 4; ++j) {
                int l = l0 + j;
                float acc = y0;
                acc = fmaf(2.f * y1r, tc[l],       acc);
                acc = fmaf(2.f * y1i, ts[l],       acc);
                acc = fmaf(2.f * y2r, tc[192 + l], acc);
                acc = fmaf(2.f * y2i, ts[192 + l], acc);
                vv[j] = acc * (1.0f / 64.0f);
            }
            ((float4*)op)[f4] = v;
        }
    }
}

extern "C" void kernel_launch(void* const* d_in, const int* in_sizes, int n_in,
                              void* d_out, int out_size)
{
    // metadata order: q, k, v, mask, weights1, weights2  (k, v, mask unused)
    const float* q  = (const float*)d_in[0];
    const float* w1 = (const float*)d_in[4];
    const float* w2 = (const float*)d_in[5];
    float* out = (float*)d_out;

    dim3 grid(NB, NN);   // batch fastest: 8 consecutive CTAs reuse node n's weights via L2
    fourier_block_kernel<<<grid, 256>>>(q, w1, w2, out);
}

// round 4
// speedup vs baseline: 1.0030x; 1.0030x over previous
#include <cuda_runtime.h>

// FourierBlock: out = irfft( scatter( einsum(rfft(q)[bins 1,4,5], W1+iW2), bins 0..2 ) )
// q: (B=8, N=2000, L=64, H=4, E=16), weights: (N, H, E, E, M=3). k, v, mask unused.
//
// One CTA per node n; loops over all 8 batches so weights are read from DRAM
// exactly once (kept in registers). q-load fused with the 3-bin DFT gather.

#define NB 8
#define NN 2000
#define SLAB 4096      // L*H*E floats per (b,n)
#define WNODE 3072     // H*E*E*M floats per node per weight tensor

__global__ __launch_bounds__(256) void fourier_node_kernel(
    const float* __restrict__ q,
    const float* __restrict__ w1,
    const float* __restrict__ w2,
    float* __restrict__ out)
{
    const int n    = blockIdx.x;
    const int tid  = threadIdx.x;
    const int lane = tid & 31;
    const int warp = tid >> 5;

    // Stage-B mapping: thread owns float4-column c (hi = 4c..4c+3), row group p (l = 4p..4p+3)
    const int c = tid & 15;
    const int p = tid >> 4;

    __shared__ float4 sXp4[8][6][16];  // per-warp partial X: [warp][2m+{re,im}][c]
    __shared__ float  sX[6][64];       // X[2m+{re,im}][h*16+i]
    __shared__ float  sY[6][64];       // Y[2m+{re,im}][h*16+o]

    // ---- per-CTA twiddles (precise sincosf; trivial amortized cost) ----
    // B (analysis): e^{-i*2pi*f_m*l/64} for this thread's 4 rows l=4p+j, f={1,4,5}
    float cB[4][3], sB[4][3];
    {
        const int f[3] = {1, 4, 5};
        #pragma unroll
        for (int j = 0; j < 4; ++j)
            #pragma unroll
            for (int m = 0; m < 3; ++m) {
                int ph = (f[m] * (4 * p + j)) & 63;                // exact mod-64 reduction
                float ang = -6.2831853071795864769f * (float)ph * (1.0f / 64.0f);
                sincosf(ang, &sB[j][m], &cB[j][m]);
            }
    }
    // D (synthesis): cos/sin(2pi*l/64) and (2pi*2l/64) for l = l0..l0+3, pre-scaled by 2/64
    float c1[4], s1[4], c2[4], s2[4];
    {
        const int l0 = (tid & 15) << 2;
        #pragma unroll
        for (int j = 0; j < 4; ++j) {
            int l = l0 + j;
            float a1 = 6.2831853071795864769f * (float)l * (1.0f / 64.0f);
            float a2 = 6.2831853071795864769f * (float)((2 * l) & 63) * (1.0f / 64.0f);
            float sv, cv;
            sincosf(a1, &sv, &cv);  c1[j] = cv * 0.03125f;  s1[j] = sv * 0.03125f;
            sincosf(a2, &sv, &cv);  c2[j] = cv * 0.03125f;  s2[j] = sv * 0.03125f;
        }
    }

    // ---- weights into registers, once per CTA (reused for all 8 batches) ----
    const int m_ = tid >> 6;   // 0..2 for tid<192
    const int ho = tid & 63;
    const int h  = ho >> 4;
    const int o  = ho & 15;
    float wr[16], wi[16];
    if (tid < 192) {
        const float* w1p = w1 + (size_t)n * WNODE + h * 768;
        const float* w2p = w2 + (size_t)n * WNODE + h * 768;
        #pragma unroll
        for (int i = 0; i < 16; ++i) {
            int off = ((i << 4) + o) * 3 + m_;
            wr[i] = __ldg(w1p + off);
            wi[i] = __ldg(w2p + off);
        }
    }

    for (int b = 0; b < NB; ++b) {
        const size_t slab = ((size_t)b * NN + n) * SLAB;
        const float4* q4 = (const float4*)(q + slab);

        // ---- fused A+B: batch all 4 LDG.128 up front (MLP), then 3-bin DFT ----
        float4 v[4];
        #pragma unroll
        for (int j = 0; j < 4; ++j)
            v[j] = q4[(4 * p + j) * 16 + c];

        float ar[3][4], ai[3][4];
        #pragma unroll
        for (int m = 0; m < 3; ++m)
            #pragma unroll
            for (int x = 0; x < 4; ++x) { ar[m][x] = 0.f; ai[m][x] = 0.f; }

        #pragma unroll
        for (int j = 0; j < 4; ++j) {
            #pragma unroll
            for (int m = 0; m < 3; ++m) {
                float cc = cB[j][m], ss = sB[j][m];
                ar[m][0] = fmaf(v[j].x, cc, ar[m][0]);  ai[m][0] = fmaf(v[j].x, ss, ai[m][0]);
                ar[m][1] = fmaf(v[j].y, cc, ar[m][1]);  ai[m][1] = fmaf(v[j].y, ss, ai[m][1]);
                ar[m][2] = fmaf(v[j].z, cc, ar[m][2]);  ai[m][2] = fmaf(v[j].z, ss, ai[m][2]);
                ar[m][3] = fmaf(v[j].w, cc, ar[m][3]);  ai[m][3] = fmaf(v[j].w, ss, ai[m][3]);
            }
        }
        // combine the two p-groups living in one warp
        #pragma unroll
        for (int m = 0; m < 3; ++m)
            #pragma unroll
            for (int x = 0; x < 4; ++x) {
                ar[m][x] += __shfl_xor_sync(0xffffffffu, ar[m][x], 16);
                ai[m][x] += __shfl_xor_sync(0xffffffffu, ai[m][x], 16);
            }
        if (lane < 16) {
            #pragma unroll
            for (int m = 0; m < 3; ++m) {
                sXp4[warp][2 * m    ][lane] = make_float4(ar[m][0], ar[m][1], ar[m][2], ar[m][3]);
                sXp4[warp][2 * m + 1][lane] = make_float4(ai[m][0], ai[m][1], ai[m][2], ai[m][3]);
            }
        }
        __syncthreads();

        // ---- reduce 8 warp-partials -> X ----
        if (tid < 192) {
            const float* sf = (const float*)sXp4;
            float xr = 0.f, xi = 0.f;
            #pragma unroll
            for (int w = 0; w < 8; ++w) {
                xr += sf[w * 384 + (2 * m_    ) * 64 + ho];
                xi += sf[w * 384 + (2 * m_ + 1) * 64 + ho];
            }
            sX[2 * m_    ][ho] = xr;
            sX[2 * m_ + 1][ho] = xi;
        }
        __syncthreads();

        // ---- C: per-(node,head,mode) complex 16x16 channel mix, weights in regs ----
        if (tid < 192) {
            float yr = 0.f, yi = 0.f;
            #pragma unroll
            for (int i = 0; i < 16; ++i) {
                float xr = sX[2 * m_    ][(h << 4) + i];
                float xi = sX[2 * m_ + 1][(h << 4) + i];
                yr = fmaf(xr, wr[i], yr);  yr = fmaf(-xi, wi[i], yr);
                yi = fmaf(xr, wi[i], yi);  yi = fmaf( xi, wr[i], yi);
            }
            sY[2 * m_    ][ho] = yr;
            sY[2 * m_ + 1][ho] = yi;
        }
        __syncthreads();

        // ---- D: 3-bin irfft, twiddles from registers, coalesced float4 stores ----
        float4* o4 = (float4*)(out + slab);
        #pragma unroll
        for (int r = 0; r < 4; ++r) {
            int f4i = tid + (r << 8);
            int hd  = f4i >> 4;
            float y0  = sY[0][hd];
            float y1r = sY[2][hd], y1i = sY[3][hd];
            float y2r = sY[4][hd], y2i = sY[5][hd];
            float4 vv4;
            float* vv = &vv4.x;
            #pragma unroll
            for (int j = 0; j < 4; ++j) {
                float acc = y0 * 0.015625f;
                acc = fmaf(y1r, c1[j], acc);
                acc = fmaf(-y1i, s1[j], acc);
                acc = fmaf(y2r, c2[j], acc);
                acc = fmaf(-y2i, s2[j], acc);
                vv[j] = acc;
            }
            o4[f4i] = vv4;
        }
        // next batch's sXp4 writes happen after this iteration's first
        // __syncthreads-protected reads; sX/sY hazards likewise covered.
    }
}

extern "C" void kernel_launch(void* const* d_in, const int* in_sizes, int n_in,
                              void* d_out, int out_size)
{
    // metadata order: q, k, v, mask, weights1, weights2 (k, v, mask unused)
    const float* q  = (const float*)d_in[0];
    const float* w1 = (const float*)d_in[4];
    const float* w2 = (const float*)d_in[5];
    float* out = (float*)d_out;

    fourier_node_kernel<<<NN, 256>>>(q, w1, w2, out);
}